// round 1
// baseline (speedup 1.0000x reference)
#include <cuda_runtime.h>
#include <math.h>

// Problem constants
#define Bc   4
#define Tc   2048
#define Dc   1024
#define Hc   16
#define HDc  64
#define Mc   (Bc * Tc)          // 8192 rows
#define SCALING 0.125f          // 64^-0.5

// Scratch (allocation-free rule: __device__ globals)
__device__ float g_q[Mc * Dc];     // [B,H,T,Hd]
__device__ float g_k[Mc * Dc];     // [B,H,T,Hd]
__device__ float g_v[Mc * Dc];     // [B,H,T,Hd]
__device__ float g_attn[Mc * Dc];  // [B*T, D] row-major

// ---------------------------------------------------------------------------
// GEMM: C[M,N] = (A[M,K] @ W[K,N] + bias) * scale
// M=8192, K=N=1024. Block tile 128x128x16, 256 threads, 8x8 per thread.
// mode 0: row-major write. mode 1: write [B,H,T,Hd] (QKV head split).
// ---------------------------------------------------------------------------
__global__ __launch_bounds__(256, 2)
void gemm_f32(const float* __restrict__ A, const float* __restrict__ W,
              const float* __restrict__ bias, float* __restrict__ C,
              int mode, float scale)
{
    __shared__ float As[16][128];   // [k][m]
    __shared__ float Bs[16][128];   // [k][n]

    const int tid = threadIdx.x;
    const int tx  = tid & 15;       // 0..15
    const int ty  = tid >> 4;       // 0..15
    const int m0  = blockIdx.y * 128;
    const int n0  = blockIdx.x * 128;

    // A-tile load mapping: 128 rows x 16 k, 8 floats per thread (2 float4)
    const int arow = tid >> 1;          // 0..127
    const int ak0  = (tid & 1) * 8;     // 0 or 8
    // B-tile load mapping: 16 k-rows x 128 n, 8 floats per thread
    const int bk   = tid >> 4;          // 0..15
    const int bn0  = (tid & 15) * 8;    // 0..120

    const float* Aptr = A + (size_t)(m0 + arow) * Dc + ak0;

    float acc[8][8];
#pragma unroll
    for (int i = 0; i < 8; i++)
#pragma unroll
        for (int j = 0; j < 8; j++) acc[i][j] = 0.f;

    // Prefetch first tile into registers
    float4 na0 = *(const float4*)(Aptr);
    float4 na1 = *(const float4*)(Aptr + 4);
    float4 nb0 = *(const float4*)(W + (size_t)bk * Dc + n0 + bn0);
    float4 nb1 = *(const float4*)(W + (size_t)bk * Dc + n0 + bn0 + 4);

    for (int kt = 0; kt < Dc; kt += 16) {
        __syncthreads();
        // Store current tile to shared
        As[ak0 + 0][arow] = na0.x; As[ak0 + 1][arow] = na0.y;
        As[ak0 + 2][arow] = na0.z; As[ak0 + 3][arow] = na0.w;
        As[ak0 + 4][arow] = na1.x; As[ak0 + 5][arow] = na1.y;
        As[ak0 + 6][arow] = na1.z; As[ak0 + 7][arow] = na1.w;
        *(float4*)&Bs[bk][bn0]     = nb0;
        *(float4*)&Bs[bk][bn0 + 4] = nb1;
        __syncthreads();

        // Prefetch next tile (global loads overlap with FMA below)
        if (kt + 16 < Dc) {
            na0 = *(const float4*)(Aptr + kt + 16);
            na1 = *(const float4*)(Aptr + kt + 16 + 4);
            nb0 = *(const float4*)(W + (size_t)(kt + 16 + bk) * Dc + n0 + bn0);
            nb1 = *(const float4*)(W + (size_t)(kt + 16 + bk) * Dc + n0 + bn0 + 4);
        }

#pragma unroll
        for (int kk = 0; kk < 16; kk++) {
            float af[8], bf[8];
            *(float4*)&af[0] = *(const float4*)&As[kk][ty * 8];
            *(float4*)&af[4] = *(const float4*)&As[kk][ty * 8 + 4];
            *(float4*)&bf[0] = *(const float4*)&Bs[kk][tx * 8];
            *(float4*)&bf[4] = *(const float4*)&Bs[kk][tx * 8 + 4];
#pragma unroll
            for (int i = 0; i < 8; i++)
#pragma unroll
                for (int j = 0; j < 8; j++)
                    acc[i][j] = fmaf(af[i], bf[j], acc[i][j]);
        }
    }

    // Epilogue
#pragma unroll
    for (int i = 0; i < 8; i++) {
        const int m = m0 + ty * 8 + i;
        const int b = m >> 11;        // / 2048
        const int t = m & 2047;
#pragma unroll
        for (int j = 0; j < 8; j++) {
            const int n = n0 + tx * 8 + j;
            const float v = (acc[i][j] + bias[n]) * scale;
            if (mode == 0) {
                C[(size_t)m * Dc + n] = v;
            } else {
                const int h  = n >> 6;
                const int hd = n & 63;
                C[(((size_t)(b * Hc + h)) * Tc + t) * HDc + hd] = v;
            }
        }
    }
}

// ---------------------------------------------------------------------------
// Flash attention (fp32, online softmax). One block = 64 query rows of one
// (b,h). 256 threads as 16x16, each owns a 4x4 tile of the 64x64 score block
// and a 4x4 tile of the 64-wide output accumulator.
// ---------------------------------------------------------------------------
#define FA_PAD 65
#define FA_SMEM (4 * 64 * FA_PAD * 4)   // 66560 bytes

__global__ __launch_bounds__(256, 2)
void flash_attn(const float* __restrict__ Q, const float* __restrict__ K,
                const float* __restrict__ V, const float* __restrict__ Msk,
                float* __restrict__ Out)
{
    extern __shared__ float smx[];
    float* Qs = smx;                    // [64][65]  (r, k)
    float* Ks = smx + 64 * FA_PAD;      // [64][65]  (s, k)
    float* Vs = smx + 2 * 64 * FA_PAD;  // [64][65]  (s, d)
    float* Ps = smx + 3 * 64 * FA_PAD;  // [64][65]  (r, s)

    const int tid = threadIdx.x;
    const int tx  = tid & 15;
    const int ty  = tid >> 4;
    const int bh  = blockIdx.y;         // 0..63
    const int b   = bh >> 4;
    const int h   = bh & 15;
    const int q0  = blockIdx.x * 64;

    const float* Qg = Q + (size_t)bh * Tc * HDc + (size_t)q0 * HDc;
    const float* Kg = K + (size_t)bh * Tc * HDc;
    const float* Vg = V + (size_t)bh * Tc * HDc;
    const float* Mg = Msk + (size_t)b * Tc * Tc;

    // Load Q tile (coalesced float4, scalar-scatter into padded smem)
    for (int f = tid; f < 64 * 16; f += 256) {
        const int r = f >> 4;
        const int c = (f & 15) * 4;
        float4 v = *(const float4*)(Qg + r * HDc + c);
        Qs[r * FA_PAD + c + 0] = v.x;
        Qs[r * FA_PAD + c + 1] = v.y;
        Qs[r * FA_PAD + c + 2] = v.z;
        Qs[r * FA_PAD + c + 3] = v.w;
    }

    float o[4][4];
    float mrow[4], lrow[4];
#pragma unroll
    for (int i = 0; i < 4; i++) {
        mrow[i] = -1e30f; lrow[i] = 0.f;
#pragma unroll
        for (int j = 0; j < 4; j++) o[i][j] = 0.f;
    }

    const int r0 = ty * 4;
    const int c0 = tx * 4;

    for (int kb = 0; kb < Tc / 64; kb++) {
        __syncthreads();   // prev PV reads of Ks/Vs/Ps done; also covers Qs on kb=0
        // Load K,V tiles
        for (int f = tid; f < 64 * 16; f += 256) {
            const int r = f >> 4;
            const int c = (f & 15) * 4;
            float4 kv = *(const float4*)(Kg + (size_t)(kb * 64 + r) * HDc + c);
            float4 vv = *(const float4*)(Vg + (size_t)(kb * 64 + r) * HDc + c);
            Ks[r * FA_PAD + c + 0] = kv.x; Ks[r * FA_PAD + c + 1] = kv.y;
            Ks[r * FA_PAD + c + 2] = kv.z; Ks[r * FA_PAD + c + 3] = kv.w;
            Vs[r * FA_PAD + c + 0] = vv.x; Vs[r * FA_PAD + c + 1] = vv.y;
            Vs[r * FA_PAD + c + 2] = vv.z; Vs[r * FA_PAD + c + 3] = vv.w;
        }
        __syncthreads();

        // Scores: S = Q @ K^T + mask  (Q pre-scaled by SCALING in projection)
        float s[4][4];
#pragma unroll
        for (int i = 0; i < 4; i++)
#pragma unroll
            for (int j = 0; j < 4; j++)
                s[i][j] = Mg[(size_t)(q0 + r0 + i) * Tc + kb * 64 + c0 + j];

        for (int k = 0; k < HDc; k++) {
            float qv[4], kv[4];
#pragma unroll
            for (int i = 0; i < 4; i++) qv[i] = Qs[(r0 + i) * FA_PAD + k];
#pragma unroll
            for (int j = 0; j < 4; j++) kv[j] = Ks[(c0 + j) * FA_PAD + k];
#pragma unroll
            for (int i = 0; i < 4; i++)
#pragma unroll
                for (int j = 0; j < 4; j++)
                    s[i][j] = fmaf(qv[i], kv[j], s[i][j]);
        }

        // Online softmax update
#pragma unroll
        for (int i = 0; i < 4; i++) {
            float rmax = fmaxf(fmaxf(s[i][0], s[i][1]), fmaxf(s[i][2], s[i][3]));
#pragma unroll
            for (int off = 8; off >= 1; off >>= 1)
                rmax = fmaxf(rmax, __shfl_xor_sync(0xffffffffu, rmax, off));
            const float mnew = fmaxf(mrow[i], rmax);
            const float corr = __expf(mrow[i] - mnew);
            mrow[i] = mnew;
            float rs = 0.f;
#pragma unroll
            for (int j = 0; j < 4; j++) {
                const float p = __expf(s[i][j] - mnew);
                Ps[(r0 + i) * FA_PAD + c0 + j] = p;
                rs += p;
            }
#pragma unroll
            for (int off = 8; off >= 1; off >>= 1)
                rs += __shfl_xor_sync(0xffffffffu, rs, off);
            lrow[i] = lrow[i] * corr + rs;
#pragma unroll
            for (int j = 0; j < 4; j++) o[i][j] *= corr;
        }
        __syncthreads();   // Ps complete before PV

        // O += P @ V
        for (int ss = 0; ss < 64; ss++) {
            float pv[4], vv[4];
#pragma unroll
            for (int i = 0; i < 4; i++) pv[i] = Ps[(r0 + i) * FA_PAD + ss];
#pragma unroll
            for (int j = 0; j < 4; j++) vv[j] = Vs[ss * FA_PAD + c0 + j];
#pragma unroll
            for (int i = 0; i < 4; i++)
#pragma unroll
                for (int j = 0; j < 4; j++)
                    o[i][j] = fmaf(pv[i], vv[j], o[i][j]);
        }
    }

    // Write attention output as [B*T, D] row-major (n = h*64 + d)
    float* Og = Out + ((size_t)(b * Tc + q0)) * Dc + h * HDc;
#pragma unroll
    for (int i = 0; i < 4; i++) {
        const float inv = 1.f / lrow[i];
#pragma unroll
        for (int j = 0; j < 4; j++)
            Og[(size_t)(r0 + i) * Dc + c0 + j] = o[i][j] * inv;
    }
}

// ---------------------------------------------------------------------------
// Launch
// ---------------------------------------------------------------------------
extern "C" void kernel_launch(void* const* d_in, const int* in_sizes, int n_in,
                              void* d_out, int out_size)
{
    (void)in_sizes; (void)n_in; (void)out_size;
    const float* hs   = (const float*)d_in[0];
    const float* mask = (const float*)d_in[1];
    const float* Wq   = (const float*)d_in[2];
    const float* bq   = (const float*)d_in[3];
    const float* Wk   = (const float*)d_in[4];
    const float* bk   = (const float*)d_in[5];
    const float* Wv   = (const float*)d_in[6];
    const float* bv   = (const float*)d_in[7];
    const float* Wo   = (const float*)d_in[8];
    const float* bo   = (const float*)d_in[9];
    float* out = (float*)d_out;

    float *q, *k, *v, *attn;
    cudaGetSymbolAddress((void**)&q,    g_q);
    cudaGetSymbolAddress((void**)&k,    g_k);
    cudaGetSymbolAddress((void**)&v,    g_v);
    cudaGetSymbolAddress((void**)&attn, g_attn);

    cudaFuncSetAttribute(flash_attn,
                         cudaFuncAttributeMaxDynamicSharedMemorySize, FA_SMEM);

    dim3 gg(Dc / 128, Mc / 128);   // (8, 64)
    gemm_f32<<<gg, 256>>>(hs, Wq, bq, q, 1, SCALING);
    gemm_f32<<<gg, 256>>>(hs, Wk, bk, k, 1, 1.0f);
    gemm_f32<<<gg, 256>>>(hs, Wv, bv, v, 1, 1.0f);

    dim3 ga(Tc / 64, Bc * Hc);     // (32, 64)
    flash_attn<<<ga, 256, FA_SMEM>>>(q, k, v, mask, attn);

    gemm_f32<<<gg, 256>>>(attn, Wo, bo, out, 0, 1.0f);
}

// round 3
// speedup vs baseline: 1.4225x; 1.4225x over previous
#include <cuda_runtime.h>
#include <cstdint>
#include <math.h>

// Problem constants
#define Bc   4
#define Tc   2048
#define Dc   1024
#define Hc   16
#define HDc  64
#define Mc   (Bc * Tc)          // 8192 rows
#define SCALING 0.125f          // 64^-0.5

// Scratch (allocation-free rule: __device__ globals)
__device__ float g_q[Mc * Dc];       // [B,H,T,Hd] fp32
__device__ float g_k[Mc * Dc];       // [B,H,T,Hd] fp32
__device__ float g_v[Mc * Dc];       // [B,H,T,Hd] fp32
__device__ float g_attn[Mc * Dc];    // [B*T, D] tf32-rounded fp32
__device__ float g_hs32[Mc * Dc];    // hidden_states tf32-rounded
__device__ float g_w32[4][Dc * Dc];  // W q/k/v/o tf32-rounded, original [K][N]

// ---------------------------------------------------------------------------
// Helpers
// ---------------------------------------------------------------------------
__device__ __forceinline__ uint32_t smem_u32(const void* p) {
    uint32_t a;
    asm("{ .reg .u64 t; cvta.to.shared.u64 t, %1; cvt.u32.u64 %0, t; }"
        : "=r"(a) : "l"(p));
    return a;
}
__device__ __forceinline__ uint32_t f2tf32(float f) {
    uint32_t r; asm("cvt.rna.tf32.f32 %0, %1;" : "=r"(r) : "f"(f)); return r;
}
__device__ __forceinline__ void cp16(uint32_t dst, const void* src) {
    asm volatile("cp.async.cg.shared.global [%0], [%1], 16;"
                 :: "r"(dst), "l"(src) : "memory");
}
#define CP_COMMIT() asm volatile("cp.async.commit_group;" ::: "memory")
#define CP_WAIT1()  asm volatile("cp.async.wait_group 1;" ::: "memory")

// mma.sync m16n8k8 tf32: d += a*b (fp32 accum)
__device__ __forceinline__ void mma8(float* d, const uint32_t* a, const uint32_t* b) {
    asm volatile(
        "mma.sync.aligned.m16n8k8.row.col.f32.tf32.tf32.f32 "
        "{%0,%1,%2,%3}, {%4,%5,%6,%7}, {%8,%9}, {%0,%1,%2,%3};"
        : "+f"(d[0]), "+f"(d[1]), "+f"(d[2]), "+f"(d[3])
        : "r"(a[0]), "r"(a[1]), "r"(a[2]), "r"(a[3]), "r"(b[0]), "r"(b[1]));
}

// ---------------------------------------------------------------------------
// Elementwise tf32-RN conversion (fp32 -> tf32 bits stored as float)
// ---------------------------------------------------------------------------
__global__ void cvt_tf32(const float* __restrict__ s, float* __restrict__ d, int n)
{
    const int i = (blockIdx.x * blockDim.x + threadIdx.x) * 4;
    if (i < n) {
        float4 v = *(const float4*)(s + i);
        uint4 o;
        o.x = f2tf32(v.x); o.y = f2tf32(v.y);
        o.z = f2tf32(v.z); o.w = f2tf32(v.w);
        *(uint4*)(d + i) = o;
    }
}

// ---------------------------------------------------------------------------
// Tensor-core GEMM (mma.sync tf32): C[M,N] = (A@W + bias) * scale
// A: [M,K] tf32 bits. W: [K,N] tf32 bits. BM=BN=128, BK=16.
// 256 threads = 8 warps (4 m x 2 n), warp tile 32x64 = 2x8 m16n8k8 tiles.
// 2-stage cp.async pipeline. mode 0: row-major out; mode 1: [B,H,T,Hd].
// ---------------------------------------------------------------------------
#define BM 128
#define BN 128
#define BK 16
#define NKT (Dc / BK)     // 64
#define ASTR 20           // A smem row stride (floats), conflict-free
#define BSTR 136          // B smem row stride (floats), conflict-free

__global__ __launch_bounds__(256, 2)
void gemm_tc(const float* __restrict__ A, const float* __restrict__ W,
             const float* __restrict__ bias, float* __restrict__ C,
             int mode, float scale)
{
    __shared__ uint32_t As[2][BM * ASTR];   // 20480 B
    __shared__ uint32_t Bs[2][BK * BSTR];   // 17408 B

    const int tid  = threadIdx.x;
    const int warp = tid >> 5;
    const int lane = tid & 31;
    const int lq   = lane >> 2;   // 0..7
    const int lr   = lane & 3;    // 0..3
    const int wm   = (warp & 3) * 32;   // warp m offset 0..96
    const int wn   = (warp >> 2) * 64;  // warp n offset 0..64
    const int m0   = blockIdx.y * BM;
    const int n0   = blockIdx.x * BN;

    const float* Ag = A + (size_t)m0 * Dc;
    const float* Wg = W + n0;

    const uint32_t aBase0 = smem_u32(&As[0][0]);
    const uint32_t aBase1 = smem_u32(&As[1][0]);
    const uint32_t bBase0 = smem_u32(&Bs[0][0]);
    const uint32_t bBase1 = smem_u32(&Bs[1][0]);

    // A-load mapping: 2 float4 per thread (512 float4 total)
    const int ar  = tid >> 1;            // rows 0..127 (u adds 0; see below)
    // We use idx = u*256+tid: r=idx>>2, kc=(idx&3)*4
    // B-load mapping: r=idx>>5, nc=(idx&31)*4

#define LOAD_TILE(stage, kt)                                                   \
    do {                                                                       \
        const uint32_t ab = (stage) ? aBase1 : aBase0;                         \
        const uint32_t bb = (stage) ? bBase1 : bBase0;                         \
        _Pragma("unroll")                                                      \
        for (int u = 0; u < 2; u++) {                                          \
            const int idx = u * 256 + tid;                                     \
            const int r = idx >> 2, kc = (idx & 3) * 4;                        \
            cp16(ab + (r * ASTR + kc) * 4,                                     \
                 Ag + (size_t)r * Dc + (kt) * BK + kc);                        \
        }                                                                      \
        _Pragma("unroll")                                                      \
        for (int u = 0; u < 2; u++) {                                          \
            const int idx = u * 256 + tid;                                     \
            const int r = idx >> 5, nc = (idx & 31) * 4;                       \
            cp16(bb + (r * BSTR + nc) * 4,                                     \
                 Wg + (size_t)((kt) * BK + r) * Dc + nc);                      \
        }                                                                      \
    } while (0)

    float acc[2][8][4];
#pragma unroll
    for (int mi = 0; mi < 2; mi++)
#pragma unroll
        for (int ni = 0; ni < 8; ni++)
#pragma unroll
            for (int j = 0; j < 4; j++) acc[mi][ni][j] = 0.f;

    LOAD_TILE(0, 0); CP_COMMIT();
    LOAD_TILE(1, 1); CP_COMMIT();

    for (int kt = 0; kt < NKT; kt++) {
        CP_WAIT1();
        __syncthreads();

        const uint32_t* Ac = As[kt & 1];
        const uint32_t* Bn = Bs[kt & 1];

#pragma unroll
        for (int ks = 0; ks < 2; ks++) {
            const int k0 = ks * 8;
            uint32_t a[2][4];
#pragma unroll
            for (int mi = 0; mi < 2; mi++) {
                const int r = wm + mi * 16;
                a[mi][0] = Ac[(r + lq)     * ASTR + k0 + lr];
                a[mi][1] = Ac[(r + 8 + lq) * ASTR + k0 + lr];
                a[mi][2] = Ac[(r + lq)     * ASTR + k0 + 4 + lr];
                a[mi][3] = Ac[(r + 8 + lq) * ASTR + k0 + 4 + lr];
            }
#pragma unroll
            for (int ni = 0; ni < 8; ni++) {
                uint32_t b[2];
                b[0] = Bn[(k0 + lr)     * BSTR + wn + ni * 8 + lq];
                b[1] = Bn[(k0 + 4 + lr) * BSTR + wn + ni * 8 + lq];
                mma8(acc[0][ni], a[0], b);
                mma8(acc[1][ni], a[1], b);
            }
        }

        __syncthreads();
        if (kt + 2 < NKT) LOAD_TILE(kt & 1, kt + 2);
        CP_COMMIT();
    }

    // Epilogue: c0/c1 at (row, 2*lr), c2/c3 at (row+8, 2*lr)
#pragma unroll
    for (int mi = 0; mi < 2; mi++) {
        const int mA = m0 + wm + mi * 16 + lq;      // rows mA and mA+8
#pragma unroll
        for (int ni = 0; ni < 8; ni++) {
            const int c = n0 + wn + ni * 8 + 2 * lr;
            const float2 bv = *(const float2*)(bias + c);
            float2 v0, v1;
            v0.x = (acc[mi][ni][0] + bv.x) * scale;
            v0.y = (acc[mi][ni][1] + bv.y) * scale;
            v1.x = (acc[mi][ni][2] + bv.x) * scale;
            v1.y = (acc[mi][ni][3] + bv.y) * scale;
            if (mode == 0) {
                *(float2*)(C + (size_t)mA * Dc + c)       = v0;
                *(float2*)(C + (size_t)(mA + 8) * Dc + c) = v1;
            } else {
                const int h = c >> 6, hd = c & 63;
                const int b0i = mA >> 11, t0 = mA & 2047;
                const int b1i = (mA + 8) >> 11, t1 = (mA + 8) & 2047;
                *(float2*)(C + (((size_t)(b0i * Hc + h)) * Tc + t0) * HDc + hd) = v0;
                *(float2*)(C + (((size_t)(b1i * Hc + h)) * Tc + t1) * HDc + hd) = v1;
            }
        }
    }
}

// ---------------------------------------------------------------------------
// Flash attention (fp32, online softmax) — output tf32-rounded for O-proj
// ---------------------------------------------------------------------------
#define FA_PAD 65
#define FA_SMEM (4 * 64 * FA_PAD * 4)   // 66560 bytes

extern __shared__ float smx[];

__global__ __launch_bounds__(256, 2)
void flash_attn(const float* __restrict__ Q, const float* __restrict__ K,
                const float* __restrict__ V, const float* __restrict__ Msk,
                float* __restrict__ Out)
{
    float* Qs = smx;
    float* Ks = smx + 64 * FA_PAD;
    float* Vs = smx + 2 * 64 * FA_PAD;
    float* Ps = smx + 3 * 64 * FA_PAD;

    const int tid = threadIdx.x;
    const int tx  = tid & 15;
    const int ty  = tid >> 4;
    const int bh  = blockIdx.y;
    const int b   = bh >> 4;
    const int h   = bh & 15;
    const int q0  = blockIdx.x * 64;

    const float* Qg = Q + (size_t)bh * Tc * HDc + (size_t)q0 * HDc;
    const float* Kg = K + (size_t)bh * Tc * HDc;
    const float* Vg = V + (size_t)bh * Tc * HDc;
    const float* Mg = Msk + (size_t)b * Tc * Tc;

    for (int f = tid; f < 64 * 16; f += 256) {
        const int r = f >> 4;
        const int c = (f & 15) * 4;
        float4 v = *(const float4*)(Qg + r * HDc + c);
        Qs[r * FA_PAD + c + 0] = v.x;
        Qs[r * FA_PAD + c + 1] = v.y;
        Qs[r * FA_PAD + c + 2] = v.z;
        Qs[r * FA_PAD + c + 3] = v.w;
    }

    float o[4][4];
    float mrow[4], lrow[4];
#pragma unroll
    for (int i = 0; i < 4; i++) {
        mrow[i] = -1e30f; lrow[i] = 0.f;
#pragma unroll
        for (int j = 0; j < 4; j++) o[i][j] = 0.f;
    }

    const int r0 = ty * 4;
    const int c0 = tx * 4;

    for (int kb = 0; kb < Tc / 64; kb++) {
        __syncthreads();
        for (int f = tid; f < 64 * 16; f += 256) {
            const int r = f >> 4;
            const int c = (f & 15) * 4;
            float4 kv = *(const float4*)(Kg + (size_t)(kb * 64 + r) * HDc + c);
            float4 vv = *(const float4*)(Vg + (size_t)(kb * 64 + r) * HDc + c);
            Ks[r * FA_PAD + c + 0] = kv.x; Ks[r * FA_PAD + c + 1] = kv.y;
            Ks[r * FA_PAD + c + 2] = kv.z; Ks[r * FA_PAD + c + 3] = kv.w;
            Vs[r * FA_PAD + c + 0] = vv.x; Vs[r * FA_PAD + c + 1] = vv.y;
            Vs[r * FA_PAD + c + 2] = vv.z; Vs[r * FA_PAD + c + 3] = vv.w;
        }
        __syncthreads();

        float s[4][4];
#pragma unroll
        for (int i = 0; i < 4; i++)
#pragma unroll
            for (int j = 0; j < 4; j++)
                s[i][j] = Mg[(size_t)(q0 + r0 + i) * Tc + kb * 64 + c0 + j];

        for (int k = 0; k < HDc; k++) {
            float qv[4], kv[4];
#pragma unroll
            for (int i = 0; i < 4; i++) qv[i] = Qs[(r0 + i) * FA_PAD + k];
#pragma unroll
            for (int j = 0; j < 4; j++) kv[j] = Ks[(c0 + j) * FA_PAD + k];
#pragma unroll
            for (int i = 0; i < 4; i++)
#pragma unroll
                for (int j = 0; j < 4; j++)
                    s[i][j] = fmaf(qv[i], kv[j], s[i][j]);
        }

#pragma unroll
        for (int i = 0; i < 4; i++) {
            float rmax = fmaxf(fmaxf(s[i][0], s[i][1]), fmaxf(s[i][2], s[i][3]));
#pragma unroll
            for (int off = 8; off >= 1; off >>= 1)
                rmax = fmaxf(rmax, __shfl_xor_sync(0xffffffffu, rmax, off));
            const float mnew = fmaxf(mrow[i], rmax);
            const float corr = __expf(mrow[i] - mnew);
            mrow[i] = mnew;
            float rs = 0.f;
#pragma unroll
            for (int j = 0; j < 4; j++) {
                const float p = __expf(s[i][j] - mnew);
                Ps[(r0 + i) * FA_PAD + c0 + j] = p;
                rs += p;
            }
#pragma unroll
            for (int off = 8; off >= 1; off >>= 1)
                rs += __shfl_xor_sync(0xffffffffu, rs, off);
            lrow[i] = lrow[i] * corr + rs;
#pragma unroll
            for (int j = 0; j < 4; j++) o[i][j] *= corr;
        }
        __syncthreads();

        for (int ss = 0; ss < 64; ss++) {
            float pv[4], vv[4];
#pragma unroll
            for (int i = 0; i < 4; i++) pv[i] = Ps[(r0 + i) * FA_PAD + ss];
#pragma unroll
            for (int j = 0; j < 4; j++) vv[j] = Vs[ss * FA_PAD + c0 + j];
#pragma unroll
            for (int i = 0; i < 4; i++)
#pragma unroll
                for (int j = 0; j < 4; j++)
                    o[i][j] = fmaf(pv[i], vv[j], o[i][j]);
        }
    }

    // tf32-round the output so the O-projection can consume it directly
    float* Og = Out + ((size_t)(b * Tc + q0)) * Dc + h * HDc;
#pragma unroll
    for (int i = 0; i < 4; i++) {
        const float inv = 1.f / lrow[i];
#pragma unroll
        for (int j = 0; j < 4; j++)
            Og[(size_t)(r0 + i) * Dc + c0 + j] =
                __uint_as_float(f2tf32(o[i][j] * inv));
    }
}

// ---------------------------------------------------------------------------
// Launch
// ---------------------------------------------------------------------------
extern "C" void kernel_launch(void* const* d_in, const int* in_sizes, int n_in,
                              void* d_out, int out_size)
{
    (void)in_sizes; (void)n_in; (void)out_size;
    const float* hs   = (const float*)d_in[0];
    const float* mask = (const float*)d_in[1];
    const float* Wq   = (const float*)d_in[2];
    const float* bq   = (const float*)d_in[3];
    const float* Wk   = (const float*)d_in[4];
    const float* bk   = (const float*)d_in[5];
    const float* Wv   = (const float*)d_in[6];
    const float* bv   = (const float*)d_in[7];
    const float* Wo   = (const float*)d_in[8];
    const float* bo   = (const float*)d_in[9];
    float* out = (float*)d_out;

    float *q, *k, *v, *attn, *hs32, *w32;
    cudaGetSymbolAddress((void**)&q,    g_q);
    cudaGetSymbolAddress((void**)&k,    g_k);
    cudaGetSymbolAddress((void**)&v,    g_v);
    cudaGetSymbolAddress((void**)&attn, g_attn);
    cudaGetSymbolAddress((void**)&hs32, g_hs32);
    cudaGetSymbolAddress((void**)&w32,  g_w32);
    float* wq32 = w32;
    float* wk32 = w32 + (size_t)Dc * Dc;
    float* wv32 = w32 + (size_t)2 * Dc * Dc;
    float* wo32 = w32 + (size_t)3 * Dc * Dc;

    cudaFuncSetAttribute(flash_attn,
                         cudaFuncAttributeMaxDynamicSharedMemorySize, FA_SMEM);

    const int NW = Dc * Dc;        // 1M
    const int NH = Mc * Dc;        // 8M
    cvt_tf32<<<NW / 1024, 256>>>(Wq, wq32, NW);
    cvt_tf32<<<NW / 1024, 256>>>(Wk, wk32, NW);
    cvt_tf32<<<NW / 1024, 256>>>(Wv, wv32, NW);
    cvt_tf32<<<NW / 1024, 256>>>(Wo, wo32, NW);
    cvt_tf32<<<NH / 1024, 256>>>(hs, hs32, NH);

    dim3 gg(Dc / BN, Mc / BM);     // (8, 64)
    gemm_tc<<<gg, 256>>>(hs32, wq32, bq, q, 1, SCALING);
    gemm_tc<<<gg, 256>>>(hs32, wk32, bk, k, 1, 1.0f);
    gemm_tc<<<gg, 256>>>(hs32, wv32, bv, v, 1, 1.0f);

    dim3 ga(Tc / 64, Bc * Hc);     // (32, 64)
    flash_attn<<<ga, 256, FA_SMEM>>>(q, k, v, mask, attn);

    gemm_tc<<<gg, 256>>>(attn, wo32, bo, out, 0, 1.0f);
}

// round 4
// speedup vs baseline: 3.3856x; 2.3801x over previous
#include <cuda_runtime.h>
#include <cstdint>
#include <math.h>

// Problem constants
#define Bc   4
#define Tc   2048
#define Dc   1024
#define Hc   16
#define HDc  64
#define Mc   (Bc * Tc)          // 8192 rows
#define SCALING 0.125f          // 64^-0.5

// Scratch (allocation-free rule: __device__ globals)
__device__ float g_q[Mc * Dc];       // [B,H,T,Hd] tf32 bits
__device__ float g_k[Mc * Dc];       // [B,H,T,Hd] tf32 bits
__device__ float g_v[Mc * Dc];       // [B,H,T,Hd] tf32 bits
__device__ float g_attn[Mc * Dc];    // [B*T, D] tf32 bits
__device__ float g_hs32[Mc * Dc];    // hidden_states tf32-rounded
__device__ float g_w32[4][Dc * Dc];  // W q/k/v/o tf32-rounded, [K][N]

// ---------------------------------------------------------------------------
// Helpers
// ---------------------------------------------------------------------------
__device__ __forceinline__ uint32_t smem_u32(const void* p) {
    uint32_t a;
    asm("{ .reg .u64 t; cvta.to.shared.u64 t, %1; cvt.u32.u64 %0, t; }"
        : "=r"(a) : "l"(p));
    return a;
}
__device__ __forceinline__ uint32_t f2tf32(float f) {
    uint32_t r; asm("cvt.rna.tf32.f32 %0, %1;" : "=r"(r) : "f"(f)); return r;
}
__device__ __forceinline__ void cp16(uint32_t dst, const void* src) {
    asm volatile("cp.async.cg.shared.global [%0], [%1], 16;"
                 :: "r"(dst), "l"(src) : "memory");
}
#define CP_COMMIT() asm volatile("cp.async.commit_group;" ::: "memory")
#define CP_WAIT1()  asm volatile("cp.async.wait_group 1;" ::: "memory")

// mma.sync m16n8k8 tf32: d += a*b (fp32 accum)
__device__ __forceinline__ void mma8(float* d, const uint32_t* a, const uint32_t* b) {
    asm volatile(
        "mma.sync.aligned.m16n8k8.row.col.f32.tf32.tf32.f32 "
        "{%0,%1,%2,%3}, {%4,%5,%6,%7}, {%8,%9}, {%0,%1,%2,%3};"
        : "+f"(d[0]), "+f"(d[1]), "+f"(d[2]), "+f"(d[3])
        : "r"(a[0]), "r"(a[1]), "r"(a[2]), "r"(a[3]), "r"(b[0]), "r"(b[1]));
}

// ---------------------------------------------------------------------------
// Elementwise tf32-RN conversion
// ---------------------------------------------------------------------------
__global__ void cvt_tf32(const float* __restrict__ s, float* __restrict__ d, int n)
{
    const int i = (blockIdx.x * blockDim.x + threadIdx.x) * 4;
    if (i < n) {
        float4 v = *(const float4*)(s + i);
        uint4 o;
        o.x = f2tf32(v.x); o.y = f2tf32(v.y);
        o.z = f2tf32(v.z); o.w = f2tf32(v.w);
        *(uint4*)(d + i) = o;
    }
}

// ---------------------------------------------------------------------------
// GEMM body (mma.sync tf32): C = (A@W + bias) * scale
// mode 0: row-major fp32 out. mode 1: [B,H,T,Hd] tf32-rounded out.
// ---------------------------------------------------------------------------
#define BM 128
#define BN 128
#define BK 16
#define NKT (Dc / BK)     // 64
#define ASTR 20
#define BSTR 136

__device__ __forceinline__
void gemm_body(const float* __restrict__ A, const float* __restrict__ W,
               const float* __restrict__ bias, float* __restrict__ C,
               int mode, float scale, int m0, int n0)
{
    __shared__ uint32_t As[2][BM * ASTR];
    __shared__ uint32_t Bs[2][BK * BSTR];

    const int tid  = threadIdx.x;
    const int warp = tid >> 5;
    const int lane = tid & 31;
    const int lq   = lane >> 2;
    const int lr   = lane & 3;
    const int wm   = (warp & 3) * 32;
    const int wn   = (warp >> 2) * 64;

    const float* Ag = A + (size_t)m0 * Dc;
    const float* Wg = W + n0;

    const uint32_t aBase0 = smem_u32(&As[0][0]);
    const uint32_t aBase1 = smem_u32(&As[1][0]);
    const uint32_t bBase0 = smem_u32(&Bs[0][0]);
    const uint32_t bBase1 = smem_u32(&Bs[1][0]);

#define LOAD_TILE(stage, kt)                                                   \
    do {                                                                       \
        const uint32_t ab = (stage) ? aBase1 : aBase0;                         \
        const uint32_t bb = (stage) ? bBase1 : bBase0;                         \
        _Pragma("unroll")                                                      \
        for (int u = 0; u < 2; u++) {                                          \
            const int idx = u * 256 + tid;                                     \
            const int r = idx >> 2, kc = (idx & 3) * 4;                        \
            cp16(ab + (r * ASTR + kc) * 4,                                     \
                 Ag + (size_t)r * Dc + (kt) * BK + kc);                        \
        }                                                                      \
        _Pragma("unroll")                                                      \
        for (int u = 0; u < 2; u++) {                                          \
            const int idx = u * 256 + tid;                                     \
            const int r = idx >> 5, nc = (idx & 31) * 4;                       \
            cp16(bb + (r * BSTR + nc) * 4,                                     \
                 Wg + (size_t)((kt) * BK + r) * Dc + nc);                      \
        }                                                                      \
    } while (0)

    float acc[2][8][4];
#pragma unroll
    for (int mi = 0; mi < 2; mi++)
#pragma unroll
        for (int ni = 0; ni < 8; ni++)
#pragma unroll
            for (int j = 0; j < 4; j++) acc[mi][ni][j] = 0.f;

    LOAD_TILE(0, 0); CP_COMMIT();
    LOAD_TILE(1, 1); CP_COMMIT();

    for (int kt = 0; kt < NKT; kt++) {
        CP_WAIT1();
        __syncthreads();

        const uint32_t* Ac = As[kt & 1];
        const uint32_t* Bn = Bs[kt & 1];

#pragma unroll
        for (int ks = 0; ks < 2; ks++) {
            const int k0 = ks * 8;
            uint32_t a[2][4];
#pragma unroll
            for (int mi = 0; mi < 2; mi++) {
                const int r = wm + mi * 16;
                a[mi][0] = Ac[(r + lq)     * ASTR + k0 + lr];
                a[mi][1] = Ac[(r + 8 + lq) * ASTR + k0 + lr];
                a[mi][2] = Ac[(r + lq)     * ASTR + k0 + 4 + lr];
                a[mi][3] = Ac[(r + 8 + lq) * ASTR + k0 + 4 + lr];
            }
#pragma unroll
            for (int ni = 0; ni < 8; ni++) {
                uint32_t b[2];
                b[0] = Bn[(k0 + lr)     * BSTR + wn + ni * 8 + lq];
                b[1] = Bn[(k0 + 4 + lr) * BSTR + wn + ni * 8 + lq];
                mma8(acc[0][ni], a[0], b);
                mma8(acc[1][ni], a[1], b);
            }
        }

        __syncthreads();
        if (kt + 2 < NKT) LOAD_TILE(kt & 1, kt + 2);
        CP_COMMIT();
    }
#undef LOAD_TILE

#pragma unroll
    for (int mi = 0; mi < 2; mi++) {
        const int mA = m0 + wm + mi * 16 + lq;
#pragma unroll
        for (int ni = 0; ni < 8; ni++) {
            const int c = n0 + wn + ni * 8 + 2 * lr;
            const float2 bv = *(const float2*)(bias + c);
            float2 v0, v1;
            v0.x = (acc[mi][ni][0] + bv.x) * scale;
            v0.y = (acc[mi][ni][1] + bv.y) * scale;
            v1.x = (acc[mi][ni][2] + bv.x) * scale;
            v1.y = (acc[mi][ni][3] + bv.y) * scale;
            if (mode == 0) {
                *(float2*)(C + (size_t)mA * Dc + c)       = v0;
                *(float2*)(C + (size_t)(mA + 8) * Dc + c) = v1;
            } else {
                v0.x = __uint_as_float(f2tf32(v0.x));
                v0.y = __uint_as_float(f2tf32(v0.y));
                v1.x = __uint_as_float(f2tf32(v1.x));
                v1.y = __uint_as_float(f2tf32(v1.y));
                const int h = c >> 6, hd = c & 63;
                const int b0i = mA >> 11, t0 = mA & 2047;
                const int b1i = (mA + 8) >> 11, t1 = (mA + 8) & 2047;
                *(float2*)(C + (((size_t)(b0i * Hc + h)) * Tc + t0) * HDc + hd) = v0;
                *(float2*)(C + (((size_t)(b1i * Hc + h)) * Tc + t1) * HDc + hd) = v1;
            }
        }
    }
}

// QKV fused launch: blockIdx.z selects projection
__global__ __launch_bounds__(256, 2)
void gemm_qkv(const float* __restrict__ A,
              const float* __restrict__ W0, const float* __restrict__ W1,
              const float* __restrict__ W2,
              const float* __restrict__ b0, const float* __restrict__ b1,
              const float* __restrict__ b2,
              float* __restrict__ C0, float* __restrict__ C1,
              float* __restrict__ C2)
{
    const int z = blockIdx.z;
    const float* W = (z == 0) ? W0 : (z == 1) ? W1 : W2;
    const float* bs = (z == 0) ? b0 : (z == 1) ? b1 : b2;
    float* C = (z == 0) ? C0 : (z == 1) ? C1 : C2;
    const float scale = (z == 0) ? SCALING : 1.0f;
    gemm_body(A, W, bs, C, 1, scale, blockIdx.y * BM, blockIdx.x * BN);
}

__global__ __launch_bounds__(256, 2)
void gemm_oproj(const float* __restrict__ A, const float* __restrict__ W,
                const float* __restrict__ bias, float* __restrict__ C)
{
    gemm_body(A, W, bias, C, 0, 1.0f, blockIdx.y * BM, blockIdx.x * BN);
}

// ---------------------------------------------------------------------------
// Flash attention with tf32 mma.sync.
// Block: 128 q-rows of one (b,h), 8 warps (warp w owns rows w*16..w*16+15).
// KV tiles of 64. Q/K/V/attn hold tf32 bits already.
// ---------------------------------------------------------------------------
#define QSTR 68   // stride for Qs/Ks/Ps: bank = 4*lq+lr (bijective)
#define VSTR 72   // stride for Vs: bank = 8*lr+lq (bijective)
#define QS_OFF 0
#define KS_OFF (128 * QSTR)                 // 8704
#define VS_OFF (KS_OFF + 64 * QSTR)         // 13056
#define PS_OFF (VS_OFF + 64 * VSTR)         // 17664
#define FA_SMEM ((PS_OFF + 128 * QSTR) * 4) // 105472 bytes

extern __shared__ uint32_t smu[];

__global__ __launch_bounds__(256)
void flash_tc(const float* __restrict__ Q, const float* __restrict__ K,
              const float* __restrict__ V, const float* __restrict__ Msk,
              float* __restrict__ Out)
{
    uint32_t* Qs = smu + QS_OFF;
    uint32_t* Ks = smu + KS_OFF;
    uint32_t* Vs = smu + VS_OFF;
    uint32_t* Ps = smu + PS_OFF;

    const int tid  = threadIdx.x;
    const int warp = tid >> 5;
    const int lane = tid & 31;
    const int lq   = lane >> 2;
    const int lr   = lane & 3;
    const int wm   = warp * 16;

    const int bh = blockIdx.y;
    const int b  = bh >> 4;
    const int h  = bh & 15;
    const int q0 = blockIdx.x * 128;

    const float* Qg = Q + (size_t)bh * Tc * HDc + (size_t)q0 * HDc;
    const float* Kg = K + (size_t)bh * Tc * HDc;
    const float* Vg = V + (size_t)bh * Tc * HDc;
    const float* Mg = Msk + (size_t)b * Tc * Tc;

    // Load Q tile: 128 rows x 64 cols (bits already tf32)
#pragma unroll
    for (int u = 0; u < 8; u++) {
        const int f = u * 256 + tid;
        const int r = f >> 4, c = (f & 15) * 4;
        const uint4 v = *(const uint4*)((const uint32_t*)Qg + r * HDc + c);
        Qs[r * QSTR + c + 0] = v.x; Qs[r * QSTR + c + 1] = v.y;
        Qs[r * QSTR + c + 2] = v.z; Qs[r * QSTR + c + 3] = v.w;
    }

    float o[8][4];
    float mrow[2], lrow[2];
#pragma unroll
    for (int ni = 0; ni < 8; ni++)
#pragma unroll
        for (int j = 0; j < 4; j++) o[ni][j] = 0.f;
    mrow[0] = mrow[1] = -1e30f;
    lrow[0] = lrow[1] = 0.f;

    const int mrow0 = q0 + wm + lq;       // global q row for c0/c1
    const int mrow1 = mrow0 + 8;          // for c2/c3

    for (int kb = 0; kb < Tc / 64; kb++) {
        __syncthreads();  // prior iteration done with Ks/Vs
        // Load K,V tile (64 x 64 each)
#pragma unroll
        for (int u = 0; u < 4; u++) {
            const int f = u * 256 + tid;
            const int r = f >> 4, c = (f & 15) * 4;
            const uint4 kvv = *(const uint4*)((const uint32_t*)Kg + (size_t)(kb * 64 + r) * HDc + c);
            const uint4 vvv = *(const uint4*)((const uint32_t*)Vg + (size_t)(kb * 64 + r) * HDc + c);
            Ks[r * QSTR + c + 0] = kvv.x; Ks[r * QSTR + c + 1] = kvv.y;
            Ks[r * QSTR + c + 2] = kvv.z; Ks[r * QSTR + c + 3] = kvv.w;
            Vs[r * VSTR + c + 0] = vvv.x; Vs[r * VSTR + c + 1] = vvv.y;
            Vs[r * VSTR + c + 2] = vvv.z; Vs[r * VSTR + c + 3] = vvv.w;
        }
        __syncthreads();

        // S = Q @ K^T  (16 x 64 per warp)
        float s[8][4];
#pragma unroll
        for (int ni = 0; ni < 8; ni++)
#pragma unroll
            for (int j = 0; j < 4; j++) s[ni][j] = 0.f;

#pragma unroll
        for (int ks = 0; ks < 8; ks++) {
            const int k0 = ks * 8;
            uint32_t a[4];
            a[0] = Qs[(wm + lq)     * QSTR + k0 + lr];
            a[1] = Qs[(wm + 8 + lq) * QSTR + k0 + lr];
            a[2] = Qs[(wm + lq)     * QSTR + k0 + 4 + lr];
            a[3] = Qs[(wm + 8 + lq) * QSTR + k0 + 4 + lr];
#pragma unroll
            for (int ni = 0; ni < 8; ni++) {
                uint32_t bfr[2];
                bfr[0] = Ks[(ni * 8 + lq) * QSTR + k0 + lr];
                bfr[1] = Ks[(ni * 8 + lq) * QSTR + k0 + 4 + lr];
                mma8(s[ni], a, bfr);
            }
        }

        // Add mask
#pragma unroll
        for (int ni = 0; ni < 8; ni++) {
            const int c = kb * 64 + ni * 8 + 2 * lr;
            const float2 m0 = *(const float2*)(Mg + (size_t)mrow0 * Tc + c);
            const float2 m1 = *(const float2*)(Mg + (size_t)mrow1 * Tc + c);
            s[ni][0] += m0.x; s[ni][1] += m0.y;
            s[ni][2] += m1.x; s[ni][3] += m1.y;
        }

        // Online softmax (two rows per thread: c0/c1 -> row lq, c2/c3 -> lq+8)
#pragma unroll
        for (int r = 0; r < 2; r++) {
            const int j0 = r * 2;
            float rmax = -1e30f;
#pragma unroll
            for (int ni = 0; ni < 8; ni++)
                rmax = fmaxf(rmax, fmaxf(s[ni][j0], s[ni][j0 + 1]));
            rmax = fmaxf(rmax, __shfl_xor_sync(0xffffffffu, rmax, 1));
            rmax = fmaxf(rmax, __shfl_xor_sync(0xffffffffu, rmax, 2));
            const float mnew = fmaxf(mrow[r], rmax);
            const float corr = __expf(mrow[r] - mnew);
            mrow[r] = mnew;
            float rs = 0.f;
#pragma unroll
            for (int ni = 0; ni < 8; ni++) {
                const float p0 = __expf(s[ni][j0]     - mnew);
                const float p1 = __expf(s[ni][j0 + 1] - mnew);
                s[ni][j0] = p0; s[ni][j0 + 1] = p1;
                rs += p0 + p1;
            }
            rs += __shfl_xor_sync(0xffffffffu, rs, 1);
            rs += __shfl_xor_sync(0xffffffffu, rs, 2);
            lrow[r] = lrow[r] * corr + rs;
#pragma unroll
            for (int ni = 0; ni < 8; ni++) {
                o[ni][j0]     *= corr;
                o[ni][j0 + 1] *= corr;
            }
        }

        // Store P (tf32) to per-warp-private smem region
#pragma unroll
        for (int ni = 0; ni < 8; ni++) {
            const int c = ni * 8 + 2 * lr;
            uint2 p0, p1;
            p0.x = f2tf32(s[ni][0]); p0.y = f2tf32(s[ni][1]);
            p1.x = f2tf32(s[ni][2]); p1.y = f2tf32(s[ni][3]);
            *(uint2*)&Ps[(wm + lq)     * QSTR + c] = p0;
            *(uint2*)&Ps[(wm + 8 + lq) * QSTR + c] = p1;
        }
        __syncwarp();

        // O += P @ V  (16 x 64 per warp, k = 64 seq positions)
#pragma unroll
        for (int ks = 0; ks < 8; ks++) {
            const int k0 = ks * 8;
            uint32_t a[4];
            a[0] = Ps[(wm + lq)     * QSTR + k0 + lr];
            a[1] = Ps[(wm + 8 + lq) * QSTR + k0 + lr];
            a[2] = Ps[(wm + lq)     * QSTR + k0 + 4 + lr];
            a[3] = Ps[(wm + 8 + lq) * QSTR + k0 + 4 + lr];
#pragma unroll
            for (int ni = 0; ni < 8; ni++) {
                uint32_t bfr[2];
                bfr[0] = Vs[(k0 + lr)     * VSTR + ni * 8 + lq];
                bfr[1] = Vs[(k0 + 4 + lr) * VSTR + ni * 8 + lq];
                mma8(o[ni], a, bfr);
            }
        }
    }

    // Final normalize + write [B*T, D] tf32 bits (input to O-proj)
    const float inv0 = 1.f / lrow[0];
    const float inv1 = 1.f / lrow[1];
    const int t0 = q0 + wm + lq;
    const int t1 = t0 + 8;
#pragma unroll
    for (int ni = 0; ni < 8; ni++) {
        const int c = h * HDc + ni * 8 + 2 * lr;
        uint2 v0, v1;
        v0.x = f2tf32(o[ni][0] * inv0); v0.y = f2tf32(o[ni][1] * inv0);
        v1.x = f2tf32(o[ni][2] * inv1); v1.y = f2tf32(o[ni][3] * inv1);
        *(uint2*)((uint32_t*)Out + ((size_t)(b * Tc + t0)) * Dc + c) = v0;
        *(uint2*)((uint32_t*)Out + ((size_t)(b * Tc + t1)) * Dc + c) = v1;
    }
}

// ---------------------------------------------------------------------------
// Launch
// ---------------------------------------------------------------------------
extern "C" void kernel_launch(void* const* d_in, const int* in_sizes, int n_in,
                              void* d_out, int out_size)
{
    (void)in_sizes; (void)n_in; (void)out_size;
    const float* hs   = (const float*)d_in[0];
    const float* mask = (const float*)d_in[1];
    const float* Wq   = (const float*)d_in[2];
    const float* bq   = (const float*)d_in[3];
    const float* Wk   = (const float*)d_in[4];
    const float* bk   = (const float*)d_in[5];
    const float* Wv   = (const float*)d_in[6];
    const float* bv   = (const float*)d_in[7];
    const float* Wo   = (const float*)d_in[8];
    const float* bo   = (const float*)d_in[9];
    float* out = (float*)d_out;

    float *q, *k, *v, *attn, *hs32, *w32;
    cudaGetSymbolAddress((void**)&q,    g_q);
    cudaGetSymbolAddress((void**)&k,    g_k);
    cudaGetSymbolAddress((void**)&v,    g_v);
    cudaGetSymbolAddress((void**)&attn, g_attn);
    cudaGetSymbolAddress((void**)&hs32, g_hs32);
    cudaGetSymbolAddress((void**)&w32,  g_w32);
    float* wq32 = w32;
    float* wk32 = w32 + (size_t)Dc * Dc;
    float* wv32 = w32 + (size_t)2 * Dc * Dc;
    float* wo32 = w32 + (size_t)3 * Dc * Dc;

    cudaFuncSetAttribute(flash_tc,
                         cudaFuncAttributeMaxDynamicSharedMemorySize, FA_SMEM);

    const int NW = Dc * Dc;
    const int NH = Mc * Dc;
    cvt_tf32<<<NW / 1024, 256>>>(Wq, wq32, NW);
    cvt_tf32<<<NW / 1024, 256>>>(Wk, wk32, NW);
    cvt_tf32<<<NW / 1024, 256>>>(Wv, wv32, NW);
    cvt_tf32<<<NW / 1024, 256>>>(Wo, wo32, NW);
    cvt_tf32<<<NH / 1024, 256>>>(hs, hs32, NH);

    dim3 gq(Dc / BN, Mc / BM, 3);   // (8, 64, 3)
    gemm_qkv<<<gq, 256>>>(hs32, wq32, wk32, wv32, bq, bk, bv, q, k, v);

    dim3 ga(Tc / 128, Bc * Hc);     // (16, 64)
    flash_tc<<<ga, 256, FA_SMEM>>>(q, k, v, mask, attn);

    dim3 gg(Dc / BN, Mc / BM);      // (8, 64)
    gemm_oproj<<<gg, 256>>>(attn, wo32, bo, out);
}

// round 5
// speedup vs baseline: 5.2280x; 1.5442x over previous
#include <cuda_runtime.h>
#include <cuda_fp16.h>
#include <cstdint>

// Problem constants
#define Bc   4
#define Tc   2048
#define Dc   1024
#define Hc   16
#define HDc  64
#define Mc   (Bc * Tc)          // 8192 rows
#define SCALING 0.125f

// Scratch (allocation-free rule)
__device__ __half g_q[Mc * Dc];        // [B,H,T,Hd]
__device__ __half g_k[Mc * Dc];        // [B,H,T,Hd]
__device__ __half g_v[Mc * Dc];        // [B,H,T,Hd]
__device__ __half g_attn[Mc * Dc];     // [B*T, D]
__device__ __half g_hs16[Mc * Dc];     // hidden_states fp16
__device__ __half g_wt16[4][Dc * Dc];  // W^T fp16, [N][K]

// ---------------------------------------------------------------------------
// Helpers
// ---------------------------------------------------------------------------
__device__ __forceinline__ uint32_t smem_u32(const void* p) {
    uint32_t a;
    asm("{ .reg .u64 t; cvta.to.shared.u64 t, %1; cvt.u32.u64 %0, t; }"
        : "=r"(a) : "l"(p));
    return a;
}
__device__ __forceinline__ void cp16(uint32_t dst, const void* src) {
    asm volatile("cp.async.cg.shared.global [%0], [%1], 16;"
                 :: "r"(dst), "l"(src) : "memory");
}
#define CP_COMMIT() asm volatile("cp.async.commit_group;" ::: "memory")
#define CP_WAIT1()  asm volatile("cp.async.wait_group 1;" ::: "memory")
#define CP_WAIT0()  asm volatile("cp.async.wait_group 0;" ::: "memory")

// mma.sync m16n8k16 fp16 inputs, fp32 accumulate
__device__ __forceinline__ void mma16(float* d, const uint32_t* a, const uint32_t* b) {
    asm volatile(
        "mma.sync.aligned.m16n8k16.row.col.f32.f16.f16.f32 "
        "{%0,%1,%2,%3}, {%4,%5,%6,%7}, {%8,%9}, {%0,%1,%2,%3};"
        : "+f"(d[0]), "+f"(d[1]), "+f"(d[2]), "+f"(d[3])
        : "r"(a[0]), "r"(a[1]), "r"(a[2]), "r"(a[3]), "r"(b[0]), "r"(b[1]));
}
__device__ __forceinline__ uint32_t pack_h2(float x, float y) {
    __half2 h = __floats2half2_rn(x, y);
    return *(uint32_t*)&h;
}

// ---------------------------------------------------------------------------
// fp32 -> fp16 conversion (8 elems/thread)
// ---------------------------------------------------------------------------
__global__ void cvt_h(const float* __restrict__ s, __half* __restrict__ d, int n)
{
    const int i = (blockIdx.x * blockDim.x + threadIdx.x) * 8;
    if (i < n) {
        float4 a = *(const float4*)(s + i);
        float4 b = *(const float4*)(s + i + 4);
        uint4 o;
        o.x = pack_h2(a.x, a.y); o.y = pack_h2(a.z, a.w);
        o.z = pack_h2(b.x, b.y); o.w = pack_h2(b.z, b.w);
        *(uint4*)(d + i) = o;
    }
}

// Transpose W[K][N] -> Wt[N][K] fp16
__global__ void trans_cvt(const float* __restrict__ W, __half* __restrict__ Wt)
{
    __shared__ float t[32][33];
    const int x  = blockIdx.x * 32 + threadIdx.x;   // n
    const int y0 = blockIdx.y * 32;                 // k
#pragma unroll
    for (int i = threadIdx.y; i < 32; i += 8)
        t[i][threadIdx.x] = W[(size_t)(y0 + i) * Dc + x];
    __syncthreads();
    const int xo  = blockIdx.y * 32 + threadIdx.x;  // k (out col)
    const int yo0 = blockIdx.x * 32;                // n (out row)
#pragma unroll
    for (int i = threadIdx.y; i < 32; i += 8)
        Wt[(size_t)(yo0 + i) * Dc + xo] = __float2half_rn(t[threadIdx.x][i]);
}

// ---------------------------------------------------------------------------
// GEMM (fp16 mma.sync m16n8k16): C = (A @ W + bias) * scale
// A: [M][K] fp16. Wt: [N][K] fp16 (K-major!). BM=BN=128, BK=32, 3-stage.
// MODE 0: fp32 row-major out. MODE 1: fp16 [B,H,T,Hd] out.
// ---------------------------------------------------------------------------
#define GBK   32
#define GNKT  (Dc / GBK)          // 32
#define GST   20                  // uint32 row stride (16 data + 4 pad)
#define G_STAGE (128 * GST)       // 2560 u32 per tile per stage
#define GEMM_SMEM (6 * G_STAGE * 4)   // 61440 B

template<int MODE>
__device__ __forceinline__
void gemm_body(const __half* __restrict__ A, const __half* __restrict__ Wt,
               const float* __restrict__ bias, void* Cv, float scale,
               int m0, int n0)
{
    extern __shared__ uint32_t dsm[];
    uint32_t* As = dsm;                  // [3][G_STAGE]
    uint32_t* Bs = dsm + 3 * G_STAGE;    // [3][G_STAGE]

    const int tid  = threadIdx.x;
    const int warp = tid >> 5;
    const int lane = tid & 31;
    const int lq   = lane >> 2;
    const int lr   = lane & 3;
    const int wm   = (warp & 3) * 32;
    const int wn   = (warp >> 2) * 64;

    const __half* Ag = A + (size_t)m0 * Dc;
    const __half* Bg = Wt + (size_t)n0 * Dc;
    const uint32_t aAddr = smem_u32(As);
    const uint32_t bAddr = smem_u32(Bs);

#define GLOAD(st, kt)                                                          \
    do {                                                                       \
        _Pragma("unroll")                                                      \
        for (int u = 0; u < 2; u++) {                                          \
            const int idx = u * 256 + tid;                                     \
            const int r = idx >> 2, c = idx & 3;                               \
            cp16(aAddr + ((st) * G_STAGE + r * GST + c * 4) * 4,               \
                 Ag + (size_t)r * Dc + (kt) * GBK + c * 8);                    \
        }                                                                      \
        _Pragma("unroll")                                                      \
        for (int u = 0; u < 2; u++) {                                          \
            const int idx = u * 256 + tid;                                     \
            const int r = idx >> 2, c = idx & 3;                               \
            cp16(bAddr + ((st) * G_STAGE + r * GST + c * 4) * 4,               \
                 Bg + (size_t)r * Dc + (kt) * GBK + c * 8);                    \
        }                                                                      \
        CP_COMMIT();                                                           \
    } while (0)

    float acc[2][8][4];
#pragma unroll
    for (int mi = 0; mi < 2; mi++)
#pragma unroll
        for (int ni = 0; ni < 8; ni++)
#pragma unroll
            for (int j = 0; j < 4; j++) acc[mi][ni][j] = 0.f;

    GLOAD(0, 0);
    GLOAD(1, 1);

    for (int kt = 0; kt < GNKT; kt++) {
        if (kt + 1 < GNKT) { CP_WAIT1(); } else { CP_WAIT0(); }
        __syncthreads();
        if (kt + 2 < GNKT) GLOAD((kt + 2) % 3, kt + 2);

        const uint32_t* Ac = As + (kt % 3) * G_STAGE;
        const uint32_t* Bn = Bs + (kt % 3) * G_STAGE;

#pragma unroll
        for (int ks = 0; ks < 2; ks++) {
            const int k0 = ks * 8;
            uint32_t a[2][4];
#pragma unroll
            for (int mi = 0; mi < 2; mi++) {
                const int r = wm + mi * 16;
                a[mi][0] = Ac[(r + lq)     * GST + k0 + lr];
                a[mi][1] = Ac[(r + 8 + lq) * GST + k0 + lr];
                a[mi][2] = Ac[(r + lq)     * GST + k0 + 4 + lr];
                a[mi][3] = Ac[(r + 8 + lq) * GST + k0 + 4 + lr];
            }
#pragma unroll
            for (int ni = 0; ni < 8; ni++) {
                uint32_t b[2];
                b[0] = Bn[(wn + ni * 8 + lq) * GST + k0 + lr];
                b[1] = Bn[(wn + ni * 8 + lq) * GST + k0 + 4 + lr];
                mma16(acc[0][ni], a[0], b);
                mma16(acc[1][ni], a[1], b);
            }
        }
    }
#undef GLOAD

#pragma unroll
    for (int mi = 0; mi < 2; mi++) {
        const int mA = m0 + wm + mi * 16 + lq;
#pragma unroll
        for (int ni = 0; ni < 8; ni++) {
            const int c = n0 + wn + ni * 8 + 2 * lr;
            const float2 bv = *(const float2*)(bias + c);
            const float v00 = (acc[mi][ni][0] + bv.x) * scale;
            const float v01 = (acc[mi][ni][1] + bv.y) * scale;
            const float v10 = (acc[mi][ni][2] + bv.x) * scale;
            const float v11 = (acc[mi][ni][3] + bv.y) * scale;
            if (MODE == 0) {
                float* C = (float*)Cv;
                *(float2*)(C + (size_t)mA * Dc + c) = make_float2(v00, v01);
                *(float2*)(C + (size_t)(mA + 8) * Dc + c) = make_float2(v10, v11);
            } else {
                __half* C = (__half*)Cv;
                const int h = c >> 6, hd = c & 63;
                const int b0i = mA >> 11, t0 = mA & 2047;
                const int b1i = (mA + 8) >> 11, t1 = (mA + 8) & 2047;
                *(uint32_t*)(C + (((size_t)(b0i * Hc + h)) * Tc + t0) * HDc + hd)
                    = pack_h2(v00, v01);
                *(uint32_t*)(C + (((size_t)(b1i * Hc + h)) * Tc + t1) * HDc + hd)
                    = pack_h2(v10, v11);
            }
        }
    }
}

__global__ __launch_bounds__(256, 2)
void gemm_qkv(const __half* __restrict__ A,
              const __half* __restrict__ W0, const __half* __restrict__ W1,
              const __half* __restrict__ W2,
              const float* __restrict__ b0, const float* __restrict__ b1,
              const float* __restrict__ b2,
              __half* __restrict__ C0, __half* __restrict__ C1,
              __half* __restrict__ C2)
{
    const int z = blockIdx.z;
    const __half* W  = (z == 0) ? W0 : (z == 1) ? W1 : W2;
    const float*  bs = (z == 0) ? b0 : (z == 1) ? b1 : b2;
    __half* C = (z == 0) ? C0 : (z == 1) ? C1 : C2;
    const float scale = (z == 0) ? SCALING : 1.0f;
    gemm_body<1>(A, W, bs, C, scale, blockIdx.y * 128, blockIdx.x * 128);
}

__global__ __launch_bounds__(256, 2)
void gemm_oproj(const __half* __restrict__ A, const __half* __restrict__ W,
                const float* __restrict__ bias, float* __restrict__ C)
{
    gemm_body<0>(A, W, bias, C, 1.0f, blockIdx.y * 128, blockIdx.x * 128);
}

// ---------------------------------------------------------------------------
// Flash attention (fp16 mma.sync). Block: 128 q-rows of one (b,h), 8 warps.
// KV tiles of 64, double-buffered (cp.async K, reg-transposed V).
// ---------------------------------------------------------------------------
#define FST  36                       // uint32 row stride
#define QS0  0
#define KS0  (128 * FST)              // 4608
#define KBUF (64 * FST)               // 2304
#define VS0  (KS0 + 2 * KBUF)         // 9216
#define PS0  (VS0 + 2 * KBUF)         // 13824
#define FA_SMEM ((PS0 + 128 * FST) * 4)   // 73728 B

extern __shared__ uint32_t smu[];

__global__ __launch_bounds__(256, 2)
void flash_tc(const __half* __restrict__ Q, const __half* __restrict__ K,
              const __half* __restrict__ V, const float* __restrict__ Msk,
              __half* __restrict__ Out)
{
    uint32_t* Qs = smu + QS0;
    uint32_t* Ps = smu + PS0;

    const int tid  = threadIdx.x;
    const int warp = tid >> 5;
    const int lane = tid & 31;
    const int lq   = lane >> 2;
    const int lr   = lane & 3;
    const int wm   = warp * 16;
    const int sp   = tid & 31;          // V-transpose: s-pair index
    const int hd0  = (tid >> 5) * 8;    // V-transpose: head-dim base

    const int bh = blockIdx.y;
    const int b  = bh >> 4;
    const int h  = bh & 15;
    const int q0 = blockIdx.x * 128;

    const __half* Qg = Q + (size_t)bh * Tc * HDc + (size_t)q0 * HDc;
    const __half* Kg = K + (size_t)bh * Tc * HDc;
    const __half* Vg = V + (size_t)bh * Tc * HDc;
    const float*  Mg = Msk + (size_t)b * Tc * Tc;

    const uint32_t qAddr = smem_u32(smu) + QS0 * 4;
    const uint32_t kAddr = smem_u32(smu) + KS0 * 4;

    // Prologue: cp.async Q (4/thr) + K0 (2/thr), LDG+transpose V0
#pragma unroll
    for (int u = 0; u < 4; u++) {
        const int idx = u * 256 + tid;
        const int r = idx >> 3, c = idx & 7;
        cp16(qAddr + (r * FST + c * 4) * 4, Qg + (size_t)r * HDc + c * 8);
    }
#pragma unroll
    for (int u = 0; u < 2; u++) {
        const int idx = u * 256 + tid;
        const int r = idx >> 3, c = idx & 7;
        cp16(kAddr + (r * FST + c * 4) * 4, Kg + (size_t)r * HDc + c * 8);
    }
    CP_COMMIT();
    {
        const uint32_t* vp = (const uint32_t*)Vg + (size_t)(2 * sp) * 32 + (hd0 >> 1);
        uint4 va = *(const uint4*)vp;
        uint4 vb = *(const uint4*)(vp + 32);
        CP_WAIT0();
        uint32_t* Vd = smu + VS0;
        const uint32_t* aw = &va.x;
        const uint32_t* bw = &vb.x;
#pragma unroll
        for (int i = 0; i < 4; i++) {
            Vd[(hd0 + 2 * i)     * FST + sp] = __byte_perm(aw[i], bw[i], 0x5410);
            Vd[(hd0 + 2 * i + 1) * FST + sp] = __byte_perm(aw[i], bw[i], 0x7632);
        }
    }
    __syncthreads();

    float o[8][4];
    float mrow[2], lrow[2];
#pragma unroll
    for (int ni = 0; ni < 8; ni++)
#pragma unroll
        for (int j = 0; j < 4; j++) o[ni][j] = 0.f;
    mrow[0] = mrow[1] = -1e30f;
    lrow[0] = lrow[1] = 0.f;

    const int mrow0 = q0 + wm + lq;
    const int mrow1 = mrow0 + 8;

    for (int kb = 0; kb < Tc / 64; kb++) {
        const int cur = kb & 1;
        uint4 va, vb;
        const bool pre = (kb + 1 < Tc / 64);
        if (pre) {
            // issue K(kb+1) cp.async + V(kb+1) LDG early
#pragma unroll
            for (int u = 0; u < 2; u++) {
                const int idx = u * 256 + tid;
                const int r = idx >> 3, c = idx & 7;
                cp16(kAddr + ((1 - cur) * KBUF + r * FST + c * 4) * 4,
                     Kg + (size_t)((kb + 1) * 64 + r) * HDc + c * 8);
            }
            CP_COMMIT();
            const uint32_t* vp = (const uint32_t*)Vg
                + (size_t)((kb + 1) * 64 + 2 * sp) * 32 + (hd0 >> 1);
            va = *(const uint4*)vp;
            vb = *(const uint4*)(vp + 32);
        }

        // S init = mask (LDGs issue before MMA loop -> latency hidden)
        float s[8][4];
#pragma unroll
        for (int ni = 0; ni < 8; ni++) {
            const int c = kb * 64 + ni * 8 + 2 * lr;
            const float2 m0v = *(const float2*)(Mg + (size_t)mrow0 * Tc + c);
            const float2 m1v = *(const float2*)(Mg + (size_t)mrow1 * Tc + c);
            s[ni][0] = m0v.x; s[ni][1] = m0v.y;
            s[ni][2] = m1v.x; s[ni][3] = m1v.y;
        }

        // S += Q @ K^T
        const uint32_t* Kb = smu + KS0 + cur * KBUF;
#pragma unroll
        for (int ks = 0; ks < 4; ks++) {
            const int k0 = ks * 8;
            uint32_t a[4];
            a[0] = Qs[(wm + lq)     * FST + k0 + lr];
            a[1] = Qs[(wm + 8 + lq) * FST + k0 + lr];
            a[2] = Qs[(wm + lq)     * FST + k0 + 4 + lr];
            a[3] = Qs[(wm + 8 + lq) * FST + k0 + 4 + lr];
#pragma unroll
            for (int ni = 0; ni < 8; ni++) {
                uint32_t bfr[2];
                bfr[0] = Kb[(ni * 8 + lq) * FST + k0 + lr];
                bfr[1] = Kb[(ni * 8 + lq) * FST + k0 + 4 + lr];
                mma16(s[ni], a, bfr);
            }
        }

        // Online softmax
#pragma unroll
        for (int r = 0; r < 2; r++) {
            const int j0 = r * 2;
            float rmax = -1e30f;
#pragma unroll
            for (int ni = 0; ni < 8; ni++)
                rmax = fmaxf(rmax, fmaxf(s[ni][j0], s[ni][j0 + 1]));
            rmax = fmaxf(rmax, __shfl_xor_sync(0xffffffffu, rmax, 1));
            rmax = fmaxf(rmax, __shfl_xor_sync(0xffffffffu, rmax, 2));
            const float mnew = fmaxf(mrow[r], rmax);
            const float corr = __expf(mrow[r] - mnew);
            mrow[r] = mnew;
            float rs = 0.f;
#pragma unroll
            for (int ni = 0; ni < 8; ni++) {
                const float p0 = __expf(s[ni][j0]     - mnew);
                const float p1 = __expf(s[ni][j0 + 1] - mnew);
                s[ni][j0] = p0; s[ni][j0 + 1] = p1;
                rs += p0 + p1;
            }
            rs += __shfl_xor_sync(0xffffffffu, rs, 1);
            rs += __shfl_xor_sync(0xffffffffu, rs, 2);
            lrow[r] = lrow[r] * corr + rs;
#pragma unroll
            for (int ni = 0; ni < 8; ni++) {
                o[ni][j0]     *= corr;
                o[ni][j0 + 1] *= corr;
            }
        }

        // Pack P -> fp16 smem (warp-private rows)
#pragma unroll
        for (int ni = 0; ni < 8; ni++) {
            Ps[(wm + lq)     * FST + ni * 4 + lr] = pack_h2(s[ni][0], s[ni][1]);
            Ps[(wm + 8 + lq) * FST + ni * 4 + lr] = pack_h2(s[ni][2], s[ni][3]);
        }
        __syncwarp();

        // O += P @ V   (V stored transposed: Vs[hd][s-pair])
        const uint32_t* Vb = smu + VS0 + cur * KBUF;
#pragma unroll
        for (int ks = 0; ks < 4; ks++) {
            const int k0 = ks * 8;
            uint32_t a[4];
            a[0] = Ps[(wm + lq)     * FST + k0 + lr];
            a[1] = Ps[(wm + 8 + lq) * FST + k0 + lr];
            a[2] = Ps[(wm + lq)     * FST + k0 + 4 + lr];
            a[3] = Ps[(wm + 8 + lq) * FST + k0 + 4 + lr];
#pragma unroll
            for (int ni = 0; ni < 8; ni++) {
                uint32_t bfr[2];
                bfr[0] = Vb[(ni * 8 + lq) * FST + k0 + lr];
                bfr[1] = Vb[(ni * 8 + lq) * FST + k0 + 4 + lr];
                mma16(o[ni], a, bfr);
            }
        }

        if (pre) {
            CP_WAIT0();   // K(kb+1) landed
            uint32_t* Vd = smu + VS0 + (1 - cur) * KBUF;
            const uint32_t* aw = &va.x;
            const uint32_t* bw = &vb.x;
#pragma unroll
            for (int i = 0; i < 4; i++) {
                Vd[(hd0 + 2 * i)     * FST + sp] = __byte_perm(aw[i], bw[i], 0x5410);
                Vd[(hd0 + 2 * i + 1) * FST + sp] = __byte_perm(aw[i], bw[i], 0x7632);
            }
        }
        __syncthreads();
    }

    // Normalize + write fp16 [B*T, D]
    const float inv0 = 1.f / lrow[0];
    const float inv1 = 1.f / lrow[1];
    const int t0 = q0 + wm + lq;
    const int t1 = t0 + 8;
    uint32_t* Og = (uint32_t*)Out;
#pragma unroll
    for (int ni = 0; ni < 8; ni++) {
        const int cp = h * 32 + ni * 4 + lr;   // half2 column index
        Og[((size_t)(b * Tc + t0)) * 512 + cp] = pack_h2(o[ni][0] * inv0, o[ni][1] * inv0);
        Og[((size_t)(b * Tc + t1)) * 512 + cp] = pack_h2(o[ni][2] * inv1, o[ni][3] * inv1);
    }
}

// ---------------------------------------------------------------------------
// Launch
// ---------------------------------------------------------------------------
extern "C" void kernel_launch(void* const* d_in, const int* in_sizes, int n_in,
                              void* d_out, int out_size)
{
    (void)in_sizes; (void)n_in; (void)out_size;
    const float* hs   = (const float*)d_in[0];
    const float* mask = (const float*)d_in[1];
    const float* Wq   = (const float*)d_in[2];
    const float* bq   = (const float*)d_in[3];
    const float* Wk   = (const float*)d_in[4];
    const float* bk   = (const float*)d_in[5];
    const float* Wv   = (const float*)d_in[6];
    const float* bv   = (const float*)d_in[7];
    const float* Wo   = (const float*)d_in[8];
    const float* bo   = (const float*)d_in[9];
    float* out = (float*)d_out;

    __half *q, *k, *v, *attn, *hs16, *wt;
    cudaGetSymbolAddress((void**)&q,    g_q);
    cudaGetSymbolAddress((void**)&k,    g_k);
    cudaGetSymbolAddress((void**)&v,    g_v);
    cudaGetSymbolAddress((void**)&attn, g_attn);
    cudaGetSymbolAddress((void**)&hs16, g_hs16);
    cudaGetSymbolAddress((void**)&wt,   g_wt16);
    __half* wq16 = wt;
    __half* wk16 = wt + (size_t)Dc * Dc;
    __half* wv16 = wt + (size_t)2 * Dc * Dc;
    __half* wo16 = wt + (size_t)3 * Dc * Dc;

    cudaFuncSetAttribute(gemm_qkv,
                         cudaFuncAttributeMaxDynamicSharedMemorySize, GEMM_SMEM);
    cudaFuncSetAttribute(gemm_oproj,
                         cudaFuncAttributeMaxDynamicSharedMemorySize, GEMM_SMEM);
    cudaFuncSetAttribute(flash_tc,
                         cudaFuncAttributeMaxDynamicSharedMemorySize, FA_SMEM);

    const int NH = Mc * Dc;   // 8M
    cvt_h<<<NH / 2048, 256>>>(hs, hs16, NH);
    dim3 tb(32, 8), tg(Dc / 32, Dc / 32);
    trans_cvt<<<tg, tb>>>(Wq, wq16);
    trans_cvt<<<tg, tb>>>(Wk, wk16);
    trans_cvt<<<tg, tb>>>(Wv, wv16);
    trans_cvt<<<tg, tb>>>(Wo, wo16);

    dim3 gq(Dc / 128, Mc / 128, 3);   // (8, 64, 3)
    gemm_qkv<<<gq, 256, GEMM_SMEM>>>(hs16, wq16, wk16, wv16, bq, bk, bv, q, k, v);

    dim3 ga(Tc / 128, Bc * Hc);       // (16, 64)
    flash_tc<<<ga, 256, FA_SMEM>>>(q, k, v, mask, attn);

    dim3 gg(Dc / 128, Mc / 128);      // (8, 64)
    gemm_oproj<<<gg, 256, GEMM_SMEM>>>(attn, wo16, bo, out);
}